// round 4
// baseline (speedup 1.0000x reference)
#include <cuda_runtime.h>
#include <cuda_fp16.h>
#include <cstdint>

// ---------------- constants ----------------
#define IMG   224
#define BATCH 32
#define NPIX1 12544
#define NPIX2 3136
#define N1F   401408.0f
#define N2F   100352.0f

// GEMM smem geometry: rows of 32 fp16 (64B) padded to 80B stride
#define RSTRIDE 80
#define ATERM   10240          // 128 rows * 80B (one operand term)
#define BOFF    20480          // B after Ah+Al
#define STAGEB  30720          // stage: Ah, Al, B
#define DYN     61440          // two stages

// ---------------- scratch ----------------
__device__ __half g_out1[BATCH*128*NPIX1];     // fp16 pre-BN conv1 out (102 MB)
__device__ __half g_h[BATCH*128*NPIX2];        // fp16 pooled (25 MB)
__device__ __half g_w1h[128*160], g_w1l[128*160];
__device__ __half g_w2h[128*1152], g_w2l[128*1152];
__device__ int   g_win[28*8];
__device__ float g_sum1[128], g_sq1[128], g_sum2[128], g_sq2[128];

// ---------------- helpers ----------------
__device__ __forceinline__ uint32_t smem_u32(const void* p) {
    uint32_t a;
    asm("{ .reg .u64 t; cvta.to.shared.u64 t, %1; cvt.u32.u64 %0, t; }" : "=r"(a) : "l"(p));
    return a;
}
__device__ __forceinline__ void ldsm4(uint32_t addr, uint32_t* r) {
    asm volatile("ldmatrix.sync.aligned.m8n8.x4.shared.b16 {%0,%1,%2,%3}, [%4];"
        : "=r"(r[0]), "=r"(r[1]), "=r"(r[2]), "=r"(r[3]) : "r"(addr));
}
__device__ __forceinline__ void mma16816(float* c, const uint32_t* a, const uint32_t* b) {
    asm volatile("mma.sync.aligned.m16n8k16.row.col.f32.f16.f16.f32 "
        "{%0,%1,%2,%3}, {%4,%5,%6,%7}, {%8,%9}, {%0,%1,%2,%3};"
        : "+f"(c[0]), "+f"(c[1]), "+f"(c[2]), "+f"(c[3])
        : "r"(a[0]), "r"(a[1]), "r"(a[2]), "r"(a[3]), "r"(b[0]), "r"(b[1]));
}
__device__ __forceinline__ uint32_t hpack(float v0, float v1) {
    __half2 h = __floats2half2_rn(v0, v1);
    return *(uint32_t*)&h;
}

// one K=32 chunk, fp16x2 (A split hi/lo, B single), 64x32 warp tile
__device__ __forceinline__ void mma_stage(uint32_t Ab, uint32_t Bb,
                                          uint32_t Aln, uint32_t Bln,
                                          float (*acc)[4][4]) {
    #pragma unroll
    for (int h = 0; h < 2; h++) {
        uint32_t ab = Ab + h*32 + Aln;
        uint32_t bb = Bb + h*32 + Bln;
        uint32_t am[4][4], bq[4][2], t[4];
        #pragma unroll
        for (int mt = 0; mt < 4; mt++) ldsm4(ab + mt*(16*RSTRIDE), am[mt]);
        #pragma unroll
        for (int nh = 0; nh < 2; nh++) {
            ldsm4(bb + nh*(16*RSTRIDE), t);
            bq[nh*2][0] = t[0]; bq[nh*2][1] = t[1];
            bq[nh*2+1][0] = t[2]; bq[nh*2+1][1] = t[3];
        }
        #pragma unroll
        for (int mt = 0; mt < 4; mt++)
            #pragma unroll
            for (int nt = 0; nt < 4; nt++) mma16816(acc[mt][nt], am[mt], bq[nt]);
        #pragma unroll
        for (int mt = 0; mt < 4; mt++) ldsm4(ab + ATERM + mt*(16*RSTRIDE), am[mt]);
        #pragma unroll
        for (int mt = 0; mt < 4; mt++)
            #pragma unroll
            for (int nt = 0; nt < 4; nt++) mma16816(acc[mt][nt], am[mt], bq[nt]);
    }
}

#define LDGA(s) do { _Pragma("unroll") \
    for (int i = 0; i < 4; i++) areg[i] = *(const uint4*)(asrc[i] + (s)*32); } while (0)
#define STSA(buf) do { _Pragma("unroll") \
    for (int i = 0; i < 4; i++) *(uint4*)(dsm + (buf)*STAGEB + asts[i]) = areg[i]; } while (0)
#define STSB(buf) do { \
    char* bp = dsm + (buf)*STAGEB + BOFF + (tid>>1)*RSTRIDE + khalf*32; \
    *(uint4*)bp        = make_uint4(hw[0], hw[1], hw[2], hw[3]); \
    *(uint4*)(bp + 16) = make_uint4(hw[4], hw[5], hw[6], hw[7]); } while (0)

// ---------------- init ----------------
__global__ void k_init(const float* __restrict__ w1, const float* __restrict__ w2) {
    int tid = blockIdx.x * blockDim.x + threadIdx.x;
    if (tid < 128) { g_sum1[tid] = 0.f; g_sq1[tid] = 0.f; g_sum2[tid] = 0.f; g_sq2[tid] = 0.f; }
    if (tid < 128*160) {
        int oc = tid / 160, k = tid - oc*160;
        float v = (k < 147) ? w1[oc*147 + k] : 0.f;
        __half h = __float2half_rn(v);
        g_w1h[tid] = h;
        g_w1l[tid] = __float2half_rn(v - __half2float(h));
    }
    if (tid < 128*1152) {
        float v = w2[tid];
        __half h = __float2half_rn(v);
        g_w2h[tid] = h;
        g_w2l[tid] = __float2half_rn(v - __half2float(h));
    }
    if (blockIdx.x == 0 && threadIdx.x < 28) {
        int s = threadIdx.x >> 2, w = threadIdx.x & 3;
        int a = 16*s, b = a + 16, c = 224 - b, d = 224 - a;
        int t, l, bt, r;
        if      (w == 0) { t = a; l = a; bt = b; r = c; }
        else if (w == 1) { t = b; l = a; bt = d; r = b; }
        else if (w == 2) { t = c; l = b; bt = d; r = d; }
        else             { t = a; l = c; bt = c; r = d; }
        float scale = (float)(2.0 - (double)s / 6.0);
        int ti = (int)__fdiv_rn((float)(t  + 6), scale) - 3;
        int li = (int)__fdiv_rn((float)(l  + 6), scale) - 3;
        int bi = (int)__fdiv_rn((float)(bt + 6), scale) + 3;
        int ri = (int)__fdiv_rn((float)(r  + 6), scale) + 3;
        int to = t >> 1, lo = l >> 1;
        int oh = (bt >> 1) - to, oww = (r >> 1) - lo;
        int fh = (bi - ti - 7) / 2 + 1, fw = (ri - li - 7) / 2 + 1;
        int* p = g_win + threadIdx.x * 8;
        p[0]=ti; p[1]=li; p[2]=to; p[3]=lo; p[4]=oh; p[5]=oww; p[6]=fh; p[7]=fw;
    }
}

// ---------------- conv1: fp16x2 mma implicit GEMM ----------------
__global__ void __launch_bounds__(256, 1) k_conv1m(const float* __restrict__ inp) {
    extern __shared__ char dsm[];
    __shared__ int s_win[224];
    __shared__ int t_c[160];
    __shared__ signed char t_ky[160], t_kx[160];
    __shared__ float s_red[256];

    int tid = threadIdx.x, lane = tid & 31, wid = tid >> 5;
    int warp_m = wid >> 2, warp_n = wid & 3;

    if (tid < 224) s_win[tid] = g_win[tid];
    if (tid < 160) {
        int k = tid;
        if (k < 147) {
            int c = k / 49, r = k - c*49, ky = r / 7, kx = r - ky*7;
            t_c[k] = c * 50176; t_ky[k] = (signed char)ky; t_kx[k] = (signed char)kx;
        } else { t_c[k] = -1; t_ky[k] = 0; t_kx[k] = 0; }
    }
    s_red[tid] = 0.f;
    __syncthreads();

    int img = blockIdx.x / 98;
    int pixbase = (blockIdx.x - img*98) * 128;
    int pix = pixbase + (tid >> 1);
    int y = pix / 112, x = pix - y*112;
    int khalf = tid & 1;

    int bi = y >> 3, bj = x >> 3;
    int sS = min(min(bi, bj), min(13 - bi, 13 - bj));
    int b2 = 8 * (sS + 1), c2v = 112 - b2;
    int w = (y < b2 && x < c2v) ? 0 : (x < b2 ? 1 : (y >= c2v ? 2 : 3));
    const int* wp = s_win + (sS*4 + w)*8;
    int ti = wp[0], li = wp[1], to = wp[2], lo = wp[3];
    int oh = wp[4], oww = wp[5], fh = wp[6], fw = wp[7];
    int iy0 = ti + 2 * (((y - to) * fh) / oh)  - 3;
    int ix0 = li + 2 * (((x - lo) * fw) / oww) - 3;
    const float* ibase = inp + img * 150528;

    uint4 areg[4]; float breg[16]; uint32_t hw[8];
    const __half* asrc[4]; uint32_t asts[4];
    #pragma unroll
    for (int i = 0; i < 4; i++) {
        int id = tid + i*256, term = id >> 9, rem = id & 511, row = rem >> 2, c = rem & 3;
        asrc[i] = (term ? g_w1l : g_w1h) + row*160 + c*8;
        asts[i] = term*ATERM + row*RSTRIDE + c*16;
    }

    uint32_t sb = smem_u32(dsm);
    uint32_t Aln = (lane & 15)*RSTRIDE + (lane >> 4)*16;
    uint32_t Bln = ((lane >> 4)*8 + (lane & 7))*RSTRIDE + ((lane >> 3) & 1)*16;

    #define C1_LDGB(s) do { int kb = (s)*32 + khalf*16; \
        _Pragma("unroll") for (int j = 0; j < 16; j++) { \
            int k = kb + j; \
            int iy = iy0 + t_ky[k], ix = ix0 + t_kx[k]; \
            bool v = (t_c[k] >= 0) && ((unsigned)iy < 224u) && ((unsigned)ix < 224u); \
            breg[j] = v ? __ldg(ibase + t_c[k] + iy*224 + ix) : 0.f; } \
        _Pragma("unroll") for (int j = 0; j < 8; j++) hw[j] = hpack(breg[2*j], breg[2*j+1]); } while (0)

    float acc[4][4][4];
    #pragma unroll
    for (int a = 0; a < 4; a++)
        #pragma unroll
        for (int b = 0; b < 4; b++)
            #pragma unroll
            for (int c = 0; c < 4; c++) acc[a][b][c] = 0.f;

    LDGA(0); C1_LDGB(0); STSA(0); STSB(0);
    __syncthreads();
    for (int s = 0; s < 5; s++) {
        int buf = s & 1;
        if (s < 4) { LDGA(s + 1); C1_LDGB(s + 1); }
        mma_stage(sb + buf*STAGEB + warp_m*(64*RSTRIDE),
                  sb + buf*STAGEB + BOFF + warp_n*(32*RSTRIDE), Aln, Bln, acc);
        if (s < 4) { STSA(buf ^ 1); STSB(buf ^ 1); }
        __syncthreads();
    }

    int g = lane >> 2, cp = (lane & 3) * 2;
    #pragma unroll
    for (int mt = 0; mt < 4; mt++) {
        #pragma unroll
        for (int hh = 0; hh < 2; hh++) {
            int oc = warp_m*64 + mt*16 + hh*8 + g;
            float sv = 0.f, qv = 0.f;
            __half* obase = g_out1 + (size_t)(img*128 + oc)*NPIX1;
            #pragma unroll
            for (int nt = 0; nt < 4; nt++) {
                float c0 = acc[mt][nt][hh*2], c1 = acc[mt][nt][hh*2 + 1];
                int pxl = warp_n*32 + nt*8 + cp;
                *(__half2*)(obase + pixbase + pxl) = __floats2half2_rn(c0, c1);
                sv += c0 + c1; qv += c0*c0 + c1*c1;
            }
            atomicAdd(&s_red[oc], sv);
            atomicAdd(&s_red[128 + oc], qv);
        }
    }
    __syncthreads();
    if (tid < 128) {
        atomicAdd(&g_sum1[tid], s_red[tid]);
        atomicAdd(&g_sq1[tid],  s_red[128 + tid]);
    }
}

// ---------------- BN1(inline) + ReLU + 3x3 s2 p1 maxpool ----------------
__global__ void k_pool(const float* __restrict__ gamma, const float* __restrict__ beta) {
    int idx = blockIdx.x * 256 + threadIdx.x;
    if (idx >= BATCH * 128 * NPIX2) return;
    int x  = idx % 56;
    int y  = (idx / 56) % 56;
    int nc = idx / NPIX2;
    int c  = nc & 127;
    float mean = g_sum1[c] * (1.f / N1F);
    float var  = g_sq1[c]  * (1.f / N1F) - mean * mean;
    float a = __ldg(gamma + c) * rsqrtf(var + 1e-5f);
    float b = __ldg(beta + c) - a * mean;
    const __half* src = g_out1 + (size_t)nc * NPIX1;
    float m = -1e30f;
    #pragma unroll
    for (int dy = 0; dy < 3; dy++) {
        int yy = 2*y - 1 + dy;
        if ((unsigned)yy >= 112u) continue;
        #pragma unroll
        for (int dx = 0; dx < 3; dx++) {
            int xx = 2*x - 1 + dx;
            if ((unsigned)xx >= 112u) continue;
            m = fmaxf(m, fmaf(a, __half2float(src[yy*112 + xx]), b));
        }
    }
    g_h[idx] = __float2half_rn(fmaxf(m, 0.f));
}

// ---------------- conv2: fp16x2 mma implicit GEMM ----------------
__global__ void __launch_bounds__(256, 1) k_conv2m(float* __restrict__ out) {
    extern __shared__ char dsm[];
    __shared__ int t_off[1152];
    __shared__ signed char t_dy[1152], t_dx[1152];
    __shared__ float s_red[256];

    int tid = threadIdx.x, lane = tid & 31, wid = tid >> 5;
    int warp_m = wid >> 2, warp_n = wid & 3;

    for (int k = tid; k < 1152; k += 256) {
        int ic = k / 9, r = k - ic*9, dy = r/3 - 1, dx = r - (r/3)*3 - 1;
        t_off[k] = ic*3136 + dy*56 + dx;
        t_dy[k] = (signed char)dy; t_dx[k] = (signed char)dx;
    }
    s_red[tid] = 0.f;
    __syncthreads();

    int pxg = blockIdx.x*128 + (tid >> 1);
    int img = pxg / 3136, pix = pxg - img*3136;
    int y = pix / 56, x = pix - y*56;
    int khalf = tid & 1;
    const __half* hbase = g_h + (size_t)img*(128*3136) + pix;
    bool oky[3] = { y > 0, true, y < 55 };
    bool okx[3] = { x > 0, true, x < 55 };

    uint4 areg[4]; uint32_t hw[8]; unsigned short bu[16];
    const __half* asrc[4]; uint32_t asts[4];
    #pragma unroll
    for (int i = 0; i < 4; i++) {
        int id = tid + i*256, term = id >> 9, rem = id & 511, row = rem >> 2, c = rem & 3;
        asrc[i] = (term ? g_w2l : g_w2h) + row*1152 + c*8;
        asts[i] = term*ATERM + row*RSTRIDE + c*16;
    }

    uint32_t sb = smem_u32(dsm);
    uint32_t Aln = (lane & 15)*RSTRIDE + (lane >> 4)*16;
    uint32_t Bln = ((lane >> 4)*8 + (lane & 7))*RSTRIDE + ((lane >> 3) & 1)*16;

    #define C2_LDGB(s) do { int kb = (s)*32 + khalf*16; \
        _Pragma("unroll") for (int j = 0; j < 16; j++) { \
            int k = kb + j; \
            bool v = oky[t_dy[k] + 1] && okx[t_dx[k] + 1]; \
            bu[j] = v ? __half_as_ushort(__ldg(hbase + t_off[k])) : (unsigned short)0; } \
        _Pragma("unroll") for (int j = 0; j < 8; j++) \
            hw[j] = ((uint32_t)bu[2*j+1] << 16) | (uint32_t)bu[2*j]; } while (0)

    float acc[4][4][4];
    #pragma unroll
    for (int a = 0; a < 4; a++)
        #pragma unroll
        for (int b = 0; b < 4; b++)
            #pragma unroll
            for (int c = 0; c < 4; c++) acc[a][b][c] = 0.f;

    LDGA(0); C2_LDGB(0); STSA(0); STSB(0);
    __syncthreads();
    for (int s = 0; s < 36; s++) {
        int buf = s & 1;
        if (s < 35) { LDGA(s + 1); C2_LDGB(s + 1); }
        mma_stage(sb + buf*STAGEB + warp_m*(64*RSTRIDE),
                  sb + buf*STAGEB + BOFF + warp_n*(32*RSTRIDE), Aln, Bln, acc);
        if (s < 35) { STSA(buf ^ 1); STSB(buf ^ 1); }
        __syncthreads();
    }

    int g = lane >> 2, cp = (lane & 3) * 2;
    #pragma unroll
    for (int mt = 0; mt < 4; mt++) {
        #pragma unroll
        for (int hh = 0; hh < 2; hh++) {
            int oc = warp_m*64 + mt*16 + hh*8 + g;
            float sv = 0.f, qv = 0.f;
            #pragma unroll
            for (int nt = 0; nt < 4; nt++) {
                float c0 = acc[mt][nt][hh*2], c1 = acc[mt][nt][hh*2 + 1];
                int pxl = warp_n*32 + nt*8 + cp;
                int pg = blockIdx.x*128 + pxl;
                int im2 = pg / 3136, pi2 = pg - im2*3136;
                *(float2*)(out + (size_t)(im2*128 + oc)*3136 + pi2) = make_float2(c0, c1);
                sv += c0 + c1; qv += c0*c0 + c1*c1;
            }
            atomicAdd(&s_red[oc], sv);
            atomicAdd(&s_red[128 + oc], qv);
        }
    }
    __syncthreads();
    if (tid < 128) {
        atomicAdd(&g_sum2[tid], s_red[tid]);
        atomicAdd(&g_sq2[tid],  s_red[128 + tid]);
    }
}

// ---------------- BN2(inline) + ReLU in place ----------------
__global__ void k_bn2(float* __restrict__ out,
                      const float* __restrict__ gamma, const float* __restrict__ beta) {
    int idx = blockIdx.x * 256 + threadIdx.x;
    if (idx >= BATCH * 128 * NPIX2) return;
    int c = (idx / NPIX2) & 127;
    float mean = g_sum2[c] * (1.f / N2F);
    float var  = g_sq2[c]  * (1.f / N2F) - mean * mean;
    float a = __ldg(gamma + c) * rsqrtf(var + 1e-5f);
    float b = __ldg(beta + c) - a * mean;
    out[idx] = fmaxf(fmaf(a, out[idx], b), 0.f);
}

// ---------------- launch ----------------
extern "C" void kernel_launch(void* const* d_in, const int* in_sizes, int n_in,
                              void* d_out, int out_size) {
    const float* inp = (const float*)d_in[0];
    const float* w1  = (const float*)d_in[1];
    const float* g1  = (const float*)d_in[2];
    const float* b1  = (const float*)d_in[3];
    const float* w2  = (const float*)d_in[4];
    const float* g2  = (const float*)d_in[5];
    const float* b2  = (const float*)d_in[6];
    float* out = (float*)d_out;

    cudaFuncSetAttribute(k_conv1m, cudaFuncAttributeMaxDynamicSharedMemorySize, DYN);
    cudaFuncSetAttribute(k_conv2m, cudaFuncAttributeMaxDynamicSharedMemorySize, DYN);

    k_init<<<576, 256>>>(w1, w2);
    k_conv1m<<<3136, 256, DYN>>>(inp);
    k_pool<<<(BATCH*128*NPIX2 + 255) / 256, 256>>>(g1, b1);
    k_conv2m<<<784, 256, DYN>>>(out);
    k_bn2<<<(BATCH*128*NPIX2 + 255) / 256, 256>>>(out, g2, b2);
}

// round 5
// speedup vs baseline: 1.4328x; 1.4328x over previous
#include <cuda_runtime.h>
#include <cuda_fp16.h>
#include <cstdint>

// ---------------- constants ----------------
#define IMG   224
#define BATCH 32
#define NPIX1 12544
#define NPIX2 3136
#define N1F   401408.0f
#define N2F   100352.0f

#define RSTRIDE 80             // 64B data + 16B pad per 32-fp16 row
#define ATERM   10240          // 128 rows * 80B (A hi or lo)
#define BOFF    20480          // B starts after Ah+Al
#define BTERM   5120           // 64 rows * 80B (B hi or lo)
// conv1: stage = Ah+Al+Bh+Bl = 30720; conv2: stage = Ah+Al+B = 25600
#define STAGE1  30720
#define STAGE2  25600
#define DYN1    61440
#define DYN2    51200

// ---------------- scratch ----------------
__device__ __half g_out1[BATCH*128*NPIX1];
__device__ __half g_h[BATCH*128*NPIX2];
__device__ __half g_w1h[128*160], g_w1l[128*160];
__device__ __half g_w2h[128*1152], g_w2l[128*1152];
__device__ int   g_win[28*8];
__device__ float g_sum1[128], g_sq1[128], g_sum2[128], g_sq2[128];

// ---------------- helpers ----------------
__device__ __forceinline__ uint32_t smem_u32(const void* p) {
    uint32_t a;
    asm("{ .reg .u64 t; cvta.to.shared.u64 t, %1; cvt.u32.u64 %0, t; }" : "=r"(a) : "l"(p));
    return a;
}
__device__ __forceinline__ void ldsm4(uint32_t addr, uint32_t* r) {
    asm volatile("ldmatrix.sync.aligned.m8n8.x4.shared.b16 {%0,%1,%2,%3}, [%4];"
        : "=r"(r[0]), "=r"(r[1]), "=r"(r[2]), "=r"(r[3]) : "r"(addr));
}
__device__ __forceinline__ void mma16816(float* c, const uint32_t* a, const uint32_t* b) {
    asm volatile("mma.sync.aligned.m16n8k16.row.col.f32.f16.f16.f32 "
        "{%0,%1,%2,%3}, {%4,%5,%6,%7}, {%8,%9}, {%0,%1,%2,%3};"
        : "+f"(c[0]), "+f"(c[1]), "+f"(c[2]), "+f"(c[3])
        : "r"(a[0]), "r"(a[1]), "r"(a[2]), "r"(a[3]), "r"(b[0]), "r"(b[1]));
}
__device__ __forceinline__ uint32_t hpack(float v0, float v1) {
    __half2 h = __floats2half2_rn(v0, v1);
    return *(uint32_t*)&h;
}
#define CP16(dst, src) \
    asm volatile("cp.async.cg.shared.global [%0], [%1], 16;" :: "r"(dst), "l"(src) : "memory")
#define CPCOMMIT() asm volatile("cp.async.commit_group;" ::: "memory")
#define CPWAIT(n)  asm volatile("cp.async.wait_group %0;" :: "n"(n) : "memory")

// A staging via cp.async: 1024 16B chunks (Ah+Al), 4 per thread
#define CPA(WH, WL, KDIM, s, buf, STAGE) do { \
    _Pragma("unroll") for (int i = 0; i < 4; i++) { \
        int id = tid + i*256, term = id >> 9, rem = id & 511, row = rem >> 2, c = rem & 3; \
        const __half* src = (term ? (WL) : (WH)) + row*(KDIM) + (s)*32 + c*8; \
        uint32_t dst = sb + (buf)*(STAGE) + term*ATERM + row*RSTRIDE + c*16; \
        CP16(dst, src); } \
    CPCOMMIT(); } while (0)

// ---------------- init ----------------
__global__ void k_init(const float* __restrict__ w1, const float* __restrict__ w2) {
    int tid = blockIdx.x * blockDim.x + threadIdx.x;
    if (tid < 128) { g_sum1[tid] = 0.f; g_sq1[tid] = 0.f; g_sum2[tid] = 0.f; g_sq2[tid] = 0.f; }
    if (tid < 128*160) {
        int oc = tid / 160, k = tid - oc*160;
        float v = (k < 147) ? w1[oc*147 + k] : 0.f;
        __half h = __float2half_rn(v);
        g_w1h[tid] = h;
        g_w1l[tid] = __float2half_rn(v - __half2float(h));
    }
    if (tid < 128*1152) {
        float v = w2[tid];
        __half h = __float2half_rn(v);
        g_w2h[tid] = h;
        g_w2l[tid] = __float2half_rn(v - __half2float(h));
    }
    if (blockIdx.x == 0 && threadIdx.x < 28) {
        int s = threadIdx.x >> 2, w = threadIdx.x & 3;
        int a = 16*s, b = a + 16, c = 224 - b, d = 224 - a;
        int t, l, bt, r;
        if      (w == 0) { t = a; l = a; bt = b; r = c; }
        else if (w == 1) { t = b; l = a; bt = d; r = b; }
        else if (w == 2) { t = c; l = b; bt = d; r = d; }
        else             { t = a; l = c; bt = c; r = d; }
        float scale = (float)(2.0 - (double)s / 6.0);
        int ti = (int)__fdiv_rn((float)(t  + 6), scale) - 3;
        int li = (int)__fdiv_rn((float)(l  + 6), scale) - 3;
        int bi = (int)__fdiv_rn((float)(bt + 6), scale) + 3;
        int ri = (int)__fdiv_rn((float)(r  + 6), scale) + 3;
        int to = t >> 1, lo = l >> 1;
        int oh = (bt >> 1) - to, oww = (r >> 1) - lo;
        int fh = (bi - ti - 7) / 2 + 1, fw = (ri - li - 7) / 2 + 1;
        int* p = g_win + threadIdx.x * 8;
        p[0]=ti; p[1]=li; p[2]=to; p[3]=lo; p[4]=oh; p[5]=oww; p[6]=fh; p[7]=fw;
    }
}

// ---------------- conv1: fp16x3, 32x32 warp tiles, cp.async A ----------------
__global__ void __launch_bounds__(256, 2) k_conv1m(const float* __restrict__ inp) {
    extern __shared__ char dsm[];
    __shared__ int s_win[224];
    __shared__ int t_c[160];
    __shared__ signed char t_ky[160], t_kx[160];
    __shared__ float s_red[256];

    int tid = threadIdx.x, lane = tid & 31, wid = tid >> 5;
    int warp_m = wid & 3, warp_n = wid >> 2;

    if (tid < 224) s_win[tid] = g_win[tid];
    if (tid < 160) {
        int k = tid;
        if (k < 147) {
            int c = k / 49, r = k - c*49, ky = r / 7, kx = r - ky*7;
            t_c[k] = c * 50176; t_ky[k] = (signed char)ky; t_kx[k] = (signed char)kx;
        } else { t_c[k] = -1; t_ky[k] = 0; t_kx[k] = 0; }
    }
    s_red[tid] = 0.f;
    __syncthreads();

    int img = blockIdx.x / 196;
    int pixbase = (blockIdx.x - img*196) * 64;
    int pix = pixbase + (tid >> 2);       // 4 threads per pixel
    int y = pix / 112, x = pix - y*112;
    int kq = tid & 3;

    int bi = y >> 3, bj = x >> 3;
    int sS = min(min(bi, bj), min(13 - bi, 13 - bj));
    int b2 = 8 * (sS + 1), c2v = 112 - b2;
    int w = (y < b2 && x < c2v) ? 0 : (x < b2 ? 1 : (y >= c2v ? 2 : 3));
    const int* wp = s_win + (sS*4 + w)*8;
    int iy0 = wp[0] + 2 * (((y - wp[2]) * wp[6]) / wp[4]) - 3;
    int ix0 = wp[1] + 2 * (((x - wp[3]) * wp[7]) / wp[5]) - 3;
    const float* ibase = inp + img * 150528;

    uint32_t sb = smem_u32(dsm);
    uint32_t Aln = (lane & 15)*RSTRIDE + (lane >> 4)*16;
    uint32_t Bln = ((lane >> 4)*8 + (lane & 7))*RSTRIDE + ((lane >> 3) & 1)*16;
    uint32_t bsts = (tid >> 2)*RSTRIDE + kq*16;

    uint32_t hw[4], lw[4];
    #define C1_LDGB(s) do { int kb = (s)*32 + kq*8; \
        float bv[8]; \
        _Pragma("unroll") for (int j = 0; j < 8; j++) { \
            int k = kb + j; \
            int iy = iy0 + t_ky[k], ix = ix0 + t_kx[k]; \
            bool v = (t_c[k] >= 0) && ((unsigned)iy < 224u) && ((unsigned)ix < 224u); \
            bv[j] = v ? __ldg(ibase + t_c[k] + iy*224 + ix) : 0.f; } \
        _Pragma("unroll") for (int j = 0; j < 4; j++) { \
            __half h0 = __float2half_rn(bv[2*j]), h1 = __float2half_rn(bv[2*j+1]); \
            float l0 = bv[2*j] - __half2float(h0), l1 = bv[2*j+1] - __half2float(h1); \
            hw[j] = ((uint32_t)__half_as_ushort(h1) << 16) | __half_as_ushort(h0); \
            lw[j] = hpack(l0, l1); } } while (0)
    #define C1_STSB(buf) do { \
        char* bp = dsm + (buf)*STAGE1 + BOFF + bsts; \
        *(uint4*)bp           = make_uint4(hw[0], hw[1], hw[2], hw[3]); \
        *(uint4*)(bp + BTERM) = make_uint4(lw[0], lw[1], lw[2], lw[3]); } while (0)

    float acc[2][4][4];
    #pragma unroll
    for (int a = 0; a < 2; a++)
        #pragma unroll
        for (int b = 0; b < 4; b++)
            #pragma unroll
            for (int c = 0; c < 4; c++) acc[a][b][c] = 0.f;

    // prologue
    CPA(g_w1h, g_w1l, 160, 0, 0, STAGE1);
    CPA(g_w1h, g_w1l, 160, 1, 1, STAGE1);
    C1_LDGB(0);
    CPWAIT(1);
    C1_STSB(0);
    __syncthreads();

    for (int s = 0; s < 5; s++) {
        int buf = s & 1;
        if (s < 4) C1_LDGB(s + 1);
        {   // 3-term mma over stage buf
            uint32_t Ab = sb + buf*STAGE1 + warp_m*(32*RSTRIDE);
            uint32_t Bb = sb + buf*STAGE1 + BOFF + warp_n*(32*RSTRIDE);
            #pragma unroll
            for (int h = 0; h < 2; h++) {
                uint32_t ab = Ab + h*32 + Aln;
                uint32_t bb = Bb + h*32 + Bln;
                uint32_t am[2][4], bq[4][2], t[4];
                ldsm4(ab, am[0]); ldsm4(ab + 16*RSTRIDE, am[1]);
                ldsm4(bb, t); bq[0][0]=t[0]; bq[0][1]=t[1]; bq[1][0]=t[2]; bq[1][1]=t[3];
                ldsm4(bb + 16*RSTRIDE, t); bq[2][0]=t[0]; bq[2][1]=t[1]; bq[3][0]=t[2]; bq[3][1]=t[3];
                #pragma unroll
                for (int mt = 0; mt < 2; mt++)
                    #pragma unroll
                    for (int nt = 0; nt < 4; nt++) mma16816(acc[mt][nt], am[mt], bq[nt]);
                // A lo x B hi
                ldsm4(ab + ATERM, am[0]); ldsm4(ab + ATERM + 16*RSTRIDE, am[1]);
                #pragma unroll
                for (int mt = 0; mt < 2; mt++)
                    #pragma unroll
                    for (int nt = 0; nt < 4; nt++) mma16816(acc[mt][nt], am[mt], bq[nt]);
                // A hi x B lo
                ldsm4(ab, am[0]); ldsm4(ab + 16*RSTRIDE, am[1]);
                ldsm4(bb + BTERM, t); bq[0][0]=t[0]; bq[0][1]=t[1]; bq[1][0]=t[2]; bq[1][1]=t[3];
                ldsm4(bb + BTERM + 16*RSTRIDE, t); bq[2][0]=t[0]; bq[2][1]=t[1]; bq[3][0]=t[2]; bq[3][1]=t[3];
                #pragma unroll
                for (int mt = 0; mt < 2; mt++)
                    #pragma unroll
                    for (int nt = 0; nt < 4; nt++) mma16816(acc[mt][nt], am[mt], bq[nt]);
            }
        }
        if (s < 4) {
            CPWAIT(0);
            C1_STSB(buf ^ 1);
            __syncthreads();
            if (s + 2 < 5) CPA(g_w1h, g_w1l, 160, s + 2, buf, STAGE1);
        }
    }

    int g = lane >> 2, cp = (lane & 3) * 2;
    #pragma unroll
    for (int mt = 0; mt < 2; mt++) {
        #pragma unroll
        for (int hh = 0; hh < 2; hh++) {
            int oc = warp_m*32 + mt*16 + hh*8 + g;
            float sv = 0.f, qv = 0.f;
            __half* obase = g_out1 + (size_t)(img*128 + oc)*NPIX1 + pixbase;
            #pragma unroll
            for (int nt = 0; nt < 4; nt++) {
                float c0 = acc[mt][nt][hh*2], c1 = acc[mt][nt][hh*2 + 1];
                int pxl = warp_n*32 + nt*8 + cp;
                *(__half2*)(obase + pxl) = __floats2half2_rn(c0, c1);
                sv += c0 + c1; qv += c0*c0 + c1*c1;
            }
            atomicAdd(&s_red[oc], sv);
            atomicAdd(&s_red[128 + oc], qv);
        }
    }
    __syncthreads();
    if (tid < 128) {
        atomicAdd(&g_sum1[tid], s_red[tid]);
        atomicAdd(&g_sq1[tid],  s_red[128 + tid]);
    }
}

// ---------------- BN1(inline) + ReLU + 3x3 s2 p1 maxpool ----------------
__global__ void k_pool(const float* __restrict__ gamma, const float* __restrict__ beta) {
    int idx = blockIdx.x * 256 + threadIdx.x;
    if (idx >= BATCH * 128 * NPIX2) return;
    int x  = idx % 56;
    int y  = (idx / 56) % 56;
    int nc = idx / NPIX2;
    int c  = nc & 127;
    float mean = g_sum1[c] * (1.f / N1F);
    float var  = g_sq1[c]  * (1.f / N1F) - mean * mean;
    float a = __ldg(gamma + c) * rsqrtf(var + 1e-5f);
    float b = __ldg(beta + c) - a * mean;
    const __half* src = g_out1 + (size_t)nc * NPIX1;
    float m = -1e30f;
    #pragma unroll
    for (int dy = 0; dy < 3; dy++) {
        int yy = 2*y - 1 + dy;
        if ((unsigned)yy >= 112u) continue;
        #pragma unroll
        for (int dx = 0; dx < 3; dx++) {
            int xx = 2*x - 1 + dx;
            if ((unsigned)xx >= 112u) continue;
            m = fmaxf(m, fmaf(a, __half2float(src[yy*112 + xx]), b));
        }
    }
    g_h[idx] = __float2half_rn(fmaxf(m, 0.f));
}

// ---------------- conv2: fp16x2 (B exact), 32x32 warp tiles, cp.async A ----------------
__global__ void __launch_bounds__(256, 3) k_conv2m(float* __restrict__ out) {
    extern __shared__ char dsm[];
    __shared__ int t_off[1152];
    __shared__ signed char t_dy[1152], t_dx[1152];
    __shared__ float s_red[256];

    int tid = threadIdx.x, lane = tid & 31, wid = tid >> 5;
    int warp_m = wid & 3, warp_n = wid >> 2;

    for (int k = tid; k < 1152; k += 256) {
        int ic = k / 9, r = k - ic*9, dy = r/3 - 1, dx = r - (r/3)*3 - 1;
        t_off[k] = ic*3136 + dy*56 + dx;
        t_dy[k] = (signed char)dy; t_dx[k] = (signed char)dx;
    }
    s_red[tid] = 0.f;
    __syncthreads();

    int img = blockIdx.x / 49;
    int pixbase = (blockIdx.x - img*49) * 64;
    int pix = pixbase + (tid >> 2);
    int y = pix / 56, x = pix - y*56;
    int kq = tid & 3;
    const __half* hbase = g_h + (size_t)img*(128*3136) + pix;
    bool oky[3] = { y > 0, true, y < 55 };
    bool okx[3] = { x > 0, true, x < 55 };

    uint32_t sb = smem_u32(dsm);
    uint32_t Aln = (lane & 15)*RSTRIDE + (lane >> 4)*16;
    uint32_t Bln = ((lane >> 4)*8 + (lane & 7))*RSTRIDE + ((lane >> 3) & 1)*16;
    uint32_t bsts = (tid >> 2)*RSTRIDE + kq*16;

    uint32_t hw[4];
    #define C2_LDGB(s) do { int kb = (s)*32 + kq*8; \
        unsigned short bu[8]; \
        _Pragma("unroll") for (int j = 0; j < 8; j++) { \
            int k = kb + j; \
            bool v = oky[t_dy[k] + 1] && okx[t_dx[k] + 1]; \
            bu[j] = v ? __half_as_ushort(__ldg(hbase + t_off[k])) : (unsigned short)0; } \
        _Pragma("unroll") for (int j = 0; j < 4; j++) \
            hw[j] = ((uint32_t)bu[2*j+1] << 16) | (uint32_t)bu[2*j]; } while (0)
    #define C2_STSB(buf) do { \
        *(uint4*)(dsm + (buf)*STAGE2 + BOFF + bsts) = make_uint4(hw[0], hw[1], hw[2], hw[3]); } while (0)

    float acc[2][4][4];
    #pragma unroll
    for (int a = 0; a < 2; a++)
        #pragma unroll
        for (int b = 0; b < 4; b++)
            #pragma unroll
            for (int c = 0; c < 4; c++) acc[a][b][c] = 0.f;

    CPA(g_w2h, g_w2l, 1152, 0, 0, STAGE2);
    CPA(g_w2h, g_w2l, 1152, 1, 1, STAGE2);
    C2_LDGB(0);
    CPWAIT(1);
    C2_STSB(0);
    __syncthreads();

    for (int s = 0; s < 36; s++) {
        int buf = s & 1;
        if (s < 35) C2_LDGB(s + 1);
        {
            uint32_t Ab = sb + buf*STAGE2 + warp_m*(32*RSTRIDE);
            uint32_t Bb = sb + buf*STAGE2 + BOFF + warp_n*(32*RSTRIDE);
            #pragma unroll
            for (int h = 0; h < 2; h++) {
                uint32_t ab = Ab + h*32 + Aln;
                uint32_t bb = Bb + h*32 + Bln;
                uint32_t am[2][4], bq[4][2], t[4];
                ldsm4(ab, am[0]); ldsm4(ab + 16*RSTRIDE, am[1]);
                ldsm4(bb, t); bq[0][0]=t[0]; bq[0][1]=t[1]; bq[1][0]=t[2]; bq[1][1]=t[3];
                ldsm4(bb + 16*RSTRIDE, t); bq[2][0]=t[0]; bq[2][1]=t[1]; bq[3][0]=t[2]; bq[3][1]=t[3];
                #pragma unroll
                for (int mt = 0; mt < 2; mt++)
                    #pragma unroll
                    for (int nt = 0; nt < 4; nt++) mma16816(acc[mt][nt], am[mt], bq[nt]);
                ldsm4(ab + ATERM, am[0]); ldsm4(ab + ATERM + 16*RSTRIDE, am[1]);
                #pragma unroll
                for (int mt = 0; mt < 2; mt++)
                    #pragma unroll
                    for (int nt = 0; nt < 4; nt++) mma16816(acc[mt][nt], am[mt], bq[nt]);
            }
        }
        if (s < 35) {
            CPWAIT(0);
            C2_STSB(buf ^ 1);
            __syncthreads();
            if (s + 2 < 36) CPA(g_w2h, g_w2l, 1152, s + 2, buf, STAGE2);
        }
    }

    int g = lane >> 2, cp = (lane & 3) * 2;
    #pragma unroll
    for (int mt = 0; mt < 2; mt++) {
        #pragma unroll
        for (int hh = 0; hh < 2; hh++) {
            int oc = warp_m*32 + mt*16 + hh*8 + g;
            float sv = 0.f, qv = 0.f;
            float* obase = out + (size_t)(img*128 + oc)*NPIX2 + pixbase;
            #pragma unroll
            for (int nt = 0; nt < 4; nt++) {
                float c0 = acc[mt][nt][hh*2], c1 = acc[mt][nt][hh*2 + 1];
                int pxl = warp_n*32 + nt*8 + cp;
                *(float2*)(obase + pxl) = make_float2(c0, c1);
                sv += c0 + c1; qv += c0*c0 + c1*c1;
            }
            atomicAdd(&s_red[oc], sv);
            atomicAdd(&s_red[128 + oc], qv);
        }
    }
    __syncthreads();
    if (tid < 128) {
        atomicAdd(&g_sum2[tid], s_red[tid]);
        atomicAdd(&g_sq2[tid],  s_red[128 + tid]);
    }
}

// ---------------- BN2(inline) + ReLU in place ----------------
__global__ void k_bn2(float* __restrict__ out,
                      const float* __restrict__ gamma, const float* __restrict__ beta) {
    int idx = blockIdx.x * 256 + threadIdx.x;
    if (idx >= BATCH * 128 * NPIX2) return;
    int c = (idx / NPIX2) & 127;
    float mean = g_sum2[c] * (1.f / N2F);
    float var  = g_sq2[c]  * (1.f / N2F) - mean * mean;
    float a = __ldg(gamma + c) * rsqrtf(var + 1e-5f);
    float b = __ldg(beta + c) - a * mean;
    out[idx] = fmaxf(fmaf(a, out[idx], b), 0.f);
}

// ---------------- launch ----------------
extern "C" void kernel_launch(void* const* d_in, const int* in_sizes, int n_in,
                              void* d_out, int out_size) {
    const float* inp = (const float*)d_in[0];
    const float* w1  = (const float*)d_in[1];
    const float* g1  = (const float*)d_in[2];
    const float* b1  = (const float*)d_in[3];
    const float* w2  = (const float*)d_in[4];
    const float* g2  = (const float*)d_in[5];
    const float* b2  = (const float*)d_in[6];
    float* out = (float*)d_out;

    cudaFuncSetAttribute(k_conv1m, cudaFuncAttributeMaxDynamicSharedMemorySize, DYN1);
    cudaFuncSetAttribute(k_conv2m, cudaFuncAttributeMaxDynamicSharedMemorySize, DYN2);

    k_init<<<576, 256>>>(w1, w2);
    k_conv1m<<<6272, 256, DYN1>>>(inp);
    k_pool<<<(BATCH*128*NPIX2 + 255) / 256, 256>>>(g1, b1);
    k_conv2m<<<1568, 256, DYN2>>>(out);
    k_bn2<<<(BATCH*128*NPIX2 + 255) / 256, 256>>>(out, g2, b2);
}

// round 6
// speedup vs baseline: 1.9919x; 1.3902x over previous
#include <cuda_runtime.h>
#include <cuda_fp16.h>
#include <cstdint>

// ---------------- constants ----------------
#define IMG   224
#define BATCH 32
#define NPIX1 12544
#define NPIX2 3136
#define N1F   401408.0f
#define N2F   100352.0f

// conv1 smem geometry (unchanged from R5)
#define RSTRIDE 80
#define ATERM   10240
#define BOFF    20480
#define BTERM   5120
#define STAGE1  30720
#define DYN1    61440

// conv2 new geometry: swizzled, 3-stage
#define C2_BOFF  16384         // Ah 8192 + Al 8192
#define C2_STAGE 20480         // + B 32*128
#define C2_DYN   (3*C2_STAGE)  // 61440

// padded activation plane: 58 rows x 64 cols
#define PSTRIDE 64
#define PPLANE  3712           // 58*64
#define GUARD   128

// ---------------- scratch ----------------
__device__ __half g_out1[BATCH*128*NPIX1];
__device__ __half g_hp[GUARD + BATCH*128*PPLANE + GUARD];
__device__ __half g_hs[GUARD + BATCH*128*PPLANE + GUARD];   // g_hs[j] = g_hp[j+1]
__device__ __half g_w1h[128*160], g_w1l[128*160];
__device__ __half g_w2h[128*1152], g_w2l[128*1152];
__device__ int   g_win[28*8];
__device__ float g_sum1[128], g_sq1[128], g_sum2[128], g_sq2[128];

// ---------------- helpers ----------------
__device__ __forceinline__ uint32_t smem_u32(const void* p) {
    uint32_t a;
    asm("{ .reg .u64 t; cvta.to.shared.u64 t, %1; cvt.u32.u64 %0, t; }" : "=r"(a) : "l"(p));
    return a;
}
__device__ __forceinline__ void ldsm4(uint32_t addr, uint32_t* r) {
    asm volatile("ldmatrix.sync.aligned.m8n8.x4.shared.b16 {%0,%1,%2,%3}, [%4];"
        : "=r"(r[0]), "=r"(r[1]), "=r"(r[2]), "=r"(r[3]) : "r"(addr));
}
__device__ __forceinline__ void ldsm4t(uint32_t addr, uint32_t* r) {
    asm volatile("ldmatrix.sync.aligned.m8n8.x4.trans.shared.b16 {%0,%1,%2,%3}, [%4];"
        : "=r"(r[0]), "=r"(r[1]), "=r"(r[2]), "=r"(r[3]) : "r"(addr));
}
__device__ __forceinline__ void mma16816(float* c, const uint32_t* a, const uint32_t* b) {
    asm volatile("mma.sync.aligned.m16n8k16.row.col.f32.f16.f16.f32 "
        "{%0,%1,%2,%3}, {%4,%5,%6,%7}, {%8,%9}, {%0,%1,%2,%3};"
        : "+f"(c[0]), "+f"(c[1]), "+f"(c[2]), "+f"(c[3])
        : "r"(a[0]), "r"(a[1]), "r"(a[2]), "r"(a[3]), "r"(b[0]), "r"(b[1]));
}
__device__ __forceinline__ uint32_t hpack(float v0, float v1) {
    __half2 h = __floats2half2_rn(v0, v1);
    return *(uint32_t*)&h;
}
#define CP16(dst, src) \
    asm volatile("cp.async.cg.shared.global [%0], [%1], 16;" :: "r"(dst), "l"(src) : "memory")
#define CP4(dst, src) \
    asm volatile("cp.async.ca.shared.global [%0], [%1], 4;" :: "r"(dst), "l"(src) : "memory")
#define CPCOMMIT() asm volatile("cp.async.commit_group;" ::: "memory")
#define CPWAIT(n)  asm volatile("cp.async.wait_group %0;" :: "n"(n) : "memory")

// conv1 A staging (R5 layout, padded rows)
#define CPA(WH, WL, KDIM, s, buf, STAGE) do { \
    _Pragma("unroll") for (int i = 0; i < 4; i++) { \
        int id = tid + i*256, term = id >> 9, rem = id & 511, row = rem >> 2, c = rem & 3; \
        const __half* src = (term ? (WL) : (WH)) + row*(KDIM) + (s)*32 + c*8; \
        uint32_t dst = sb + (buf)*(STAGE) + term*ATERM + row*RSTRIDE + c*16; \
        CP16(dst, src); } \
    CPCOMMIT(); } while (0)

// ---------------- init ----------------
__global__ void k_init(const float* __restrict__ w1, const float* __restrict__ w2) {
    int tid = blockIdx.x * blockDim.x + threadIdx.x;
    if (tid < 128) { g_sum1[tid] = 0.f; g_sq1[tid] = 0.f; g_sum2[tid] = 0.f; g_sq2[tid] = 0.f; }
    if (tid < 128*160) {
        int oc = tid / 160, k = tid - oc*160;
        float v = (k < 147) ? w1[oc*147 + k] : 0.f;
        __half h = __float2half_rn(v);
        g_w1h[tid] = h;
        g_w1l[tid] = __float2half_rn(v - __half2float(h));
    }
    if (tid < 128*1152) {
        float v = w2[tid];
        __half h = __float2half_rn(v);
        g_w2h[tid] = h;
        g_w2l[tid] = __float2half_rn(v - __half2float(h));
    }
    if (blockIdx.x == 0 && threadIdx.x < 28) {
        int s = threadIdx.x >> 2, w = threadIdx.x & 3;
        int a = 16*s, b = a + 16, c = 224 - b, d = 224 - a;
        int t, l, bt, r;
        if      (w == 0) { t = a; l = a; bt = b; r = c; }
        else if (w == 1) { t = b; l = a; bt = d; r = b; }
        else if (w == 2) { t = c; l = b; bt = d; r = d; }
        else             { t = a; l = c; bt = c; r = d; }
        float scale = (float)(2.0 - (double)s / 6.0);
        int ti = (int)__fdiv_rn((float)(t  + 6), scale) - 3;
        int li = (int)__fdiv_rn((float)(l  + 6), scale) - 3;
        int bi = (int)__fdiv_rn((float)(bt + 6), scale) + 3;
        int ri = (int)__fdiv_rn((float)(r  + 6), scale) + 3;
        int to = t >> 1, lo = l >> 1;
        int oh = (bt >> 1) - to, oww = (r >> 1) - lo;
        int fh = (bi - ti - 7) / 2 + 1, fw = (ri - li - 7) / 2 + 1;
        int* p = g_win + threadIdx.x * 8;
        p[0]=ti; p[1]=li; p[2]=to; p[3]=lo; p[4]=oh; p[5]=oww; p[6]=fh; p[7]=fw;
    }
}

// ---------------- conv1: fp16x3, 32x32 warp tiles, cp.async A (R5, unchanged) ----------------
__global__ void __launch_bounds__(256, 2) k_conv1m(const float* __restrict__ inp) {
    extern __shared__ __align__(128) char dsm[];
    __shared__ int s_win[224];
    __shared__ int t_c[160];
    __shared__ signed char t_ky[160], t_kx[160];
    __shared__ float s_red[256];

    int tid = threadIdx.x, lane = tid & 31, wid = tid >> 5;
    int warp_m = wid & 3, warp_n = wid >> 2;

    if (tid < 224) s_win[tid] = g_win[tid];
    if (tid < 160) {
        int k = tid;
        if (k < 147) {
            int c = k / 49, r = k - c*49, ky = r / 7, kx = r - ky*7;
            t_c[k] = c * 50176; t_ky[k] = (signed char)ky; t_kx[k] = (signed char)kx;
        } else { t_c[k] = -1; t_ky[k] = 0; t_kx[k] = 0; }
    }
    s_red[tid] = 0.f;
    __syncthreads();

    int img = blockIdx.x / 196;
    int pixbase = (blockIdx.x - img*196) * 64;
    int pix = pixbase + (tid >> 2);
    int y = pix / 112, x = pix - y*112;
    int kq = tid & 3;

    int bi = y >> 3, bj = x >> 3;
    int sS = min(min(bi, bj), min(13 - bi, 13 - bj));
    int b2 = 8 * (sS + 1), c2v = 112 - b2;
    int w = (y < b2 && x < c2v) ? 0 : (x < b2 ? 1 : (y >= c2v ? 2 : 3));
    const int* wp = s_win + (sS*4 + w)*8;
    int iy0 = wp[0] + 2 * (((y - wp[2]) * wp[6]) / wp[4]) - 3;
    int ix0 = wp[1] + 2 * (((x - wp[3]) * wp[7]) / wp[5]) - 3;
    const float* ibase = inp + img * 150528;

    uint32_t sb = smem_u32(dsm);
    uint32_t Aln = (lane & 15)*RSTRIDE + (lane >> 4)*16;
    uint32_t Bln = ((lane >> 4)*8 + (lane & 7))*RSTRIDE + ((lane >> 3) & 1)*16;
    uint32_t bsts = (tid >> 2)*RSTRIDE + kq*16;

    uint32_t hw[4], lw[4];
    #define C1_LDGB(s) do { int kb = (s)*32 + kq*8; \
        float bv[8]; \
        _Pragma("unroll") for (int j = 0; j < 8; j++) { \
            int k = kb + j; \
            int iy = iy0 + t_ky[k], ix = ix0 + t_kx[k]; \
            bool v = (t_c[k] >= 0) && ((unsigned)iy < 224u) && ((unsigned)ix < 224u); \
            bv[j] = v ? __ldg(ibase + t_c[k] + iy*224 + ix) : 0.f; } \
        _Pragma("unroll") for (int j = 0; j < 4; j++) { \
            __half h0 = __float2half_rn(bv[2*j]), h1 = __float2half_rn(bv[2*j+1]); \
            float l0 = bv[2*j] - __half2float(h0), l1 = bv[2*j+1] - __half2float(h1); \
            hw[j] = ((uint32_t)__half_as_ushort(h1) << 16) | __half_as_ushort(h0); \
            lw[j] = hpack(l0, l1); } } while (0)
    #define C1_STSB(buf) do { \
        char* bp = dsm + (buf)*STAGE1 + BOFF + bsts; \
        *(uint4*)bp           = make_uint4(hw[0], hw[1], hw[2], hw[3]); \
        *(uint4*)(bp + BTERM) = make_uint4(lw[0], lw[1], lw[2], lw[3]); } while (0)

    float acc[2][4][4];
    #pragma unroll
    for (int a = 0; a < 2; a++)
        #pragma unroll
        for (int b = 0; b < 4; b++)
            #pragma unroll
            for (int c = 0; c < 4; c++) acc[a][b][c] = 0.f;

    CPA(g_w1h, g_w1l, 160, 0, 0, STAGE1);
    CPA(g_w1h, g_w1l, 160, 1, 1, STAGE1);
    C1_LDGB(0);
    CPWAIT(1);
    C1_STSB(0);
    __syncthreads();

    for (int s = 0; s < 5; s++) {
        int buf = s & 1;
        if (s < 4) C1_LDGB(s + 1);
        {
            uint32_t Ab = sb + buf*STAGE1 + warp_m*(32*RSTRIDE);
            uint32_t Bb = sb + buf*STAGE1 + BOFF + warp_n*(32*RSTRIDE);
            #pragma unroll
            for (int h = 0; h < 2; h++) {
                uint32_t ab = Ab + h*32 + Aln;
                uint32_t bb = Bb + h*32 + Bln;
                uint32_t am[2][4], bq[4][2], t[4];
                ldsm4(ab, am[0]); ldsm4(ab + 16*RSTRIDE, am[1]);
                ldsm4(bb, t); bq[0][0]=t[0]; bq[0][1]=t[1]; bq[1][0]=t[2]; bq[1][1]=t[3];
                ldsm4(bb + 16*RSTRIDE, t); bq[2][0]=t[0]; bq[2][1]=t[1]; bq[3][0]=t[2]; bq[3][1]=t[3];
                #pragma unroll
                for (int mt = 0; mt < 2; mt++)
                    #pragma unroll
                    for (int nt = 0; nt < 4; nt++) mma16816(acc[mt][nt], am[mt], bq[nt]);
                ldsm4(ab + ATERM, am[0]); ldsm4(ab + ATERM + 16*RSTRIDE, am[1]);
                #pragma unroll
                for (int mt = 0; mt < 2; mt++)
                    #pragma unroll
                    for (int nt = 0; nt < 4; nt++) mma16816(acc[mt][nt], am[mt], bq[nt]);
                ldsm4(ab, am[0]); ldsm4(ab + 16*RSTRIDE, am[1]);
                ldsm4(bb + BTERM, t); bq[0][0]=t[0]; bq[0][1]=t[1]; bq[1][0]=t[2]; bq[1][1]=t[3];
                ldsm4(bb + BTERM + 16*RSTRIDE, t); bq[2][0]=t[0]; bq[2][1]=t[1]; bq[3][0]=t[2]; bq[3][1]=t[3];
                #pragma unroll
                for (int mt = 0; mt < 2; mt++)
                    #pragma unroll
                    for (int nt = 0; nt < 4; nt++) mma16816(acc[mt][nt], am[mt], bq[nt]);
            }
        }
        if (s < 4) {
            CPWAIT(0);
            C1_STSB(buf ^ 1);
            __syncthreads();
            if (s + 2 < 5) CPA(g_w1h, g_w1l, 160, s + 2, buf, STAGE1);
        }
    }

    int g = lane >> 2, cp = (lane & 3) * 2;
    #pragma unroll
    for (int mt = 0; mt < 2; mt++) {
        #pragma unroll
        for (int hh = 0; hh < 2; hh++) {
            int oc = warp_m*32 + mt*16 + hh*8 + g;
            float sv = 0.f, qv = 0.f;
            __half* obase = g_out1 + (size_t)(img*128 + oc)*NPIX1 + pixbase;
            #pragma unroll
            for (int nt = 0; nt < 4; nt++) {
                float c0 = acc[mt][nt][hh*2], c1 = acc[mt][nt][hh*2 + 1];
                int pxl = warp_n*32 + nt*8 + cp;
                *(__half2*)(obase + pxl) = __floats2half2_rn(c0, c1);
                sv += c0 + c1; qv += c0*c0 + c1*c1;
            }
            atomicAdd(&s_red[oc], sv);
            atomicAdd(&s_red[128 + oc], qv);
        }
    }
    __syncthreads();
    if (tid < 128) {
        atomicAdd(&g_sum1[tid], s_red[tid]);
        atomicAdd(&g_sq1[tid],  s_red[128 + tid]);
    }
}

// ---------------- BN1 + ReLU + maxpool -> padded planes (hp + shifted hs) ----------------
__global__ void k_pool(const float* __restrict__ gamma, const float* __restrict__ beta) {
    int idx = blockIdx.x * 256 + threadIdx.x;
    if (idx >= BATCH * 128 * PPLANE) return;
    int nc = idx / PPLANE;
    int p  = idx - nc * PPLANE;
    int yp = p >> 6, xp = p & 63;
    float v = 0.f;
    if (yp >= 1 && yp <= 56 && xp >= 1 && xp <= 56) {
        int y = yp - 1, x = xp - 1;
        int c = nc & 127;
        float mean = g_sum1[c] * (1.f / N1F);
        float var  = g_sq1[c]  * (1.f / N1F) - mean * mean;
        float a = __ldg(gamma + c) * rsqrtf(var + 1e-5f);
        float b = __ldg(beta + c) - a * mean;
        const __half* src = g_out1 + (size_t)nc * NPIX1;
        float m = -1e30f;
        #pragma unroll
        for (int dy = 0; dy < 3; dy++) {
            int yy = 2*y - 1 + dy;
            if ((unsigned)yy >= 112u) continue;
            #pragma unroll
            for (int dx = 0; dx < 3; dx++) {
                int xx = 2*x - 1 + dx;
                if ((unsigned)xx >= 112u) continue;
                m = fmaxf(m, fmaf(a, __half2float(src[yy*112 + xx]), b));
            }
        }
        v = fmaxf(m, 0.f);
    }
    __half h = __float2half_rn(v);
    g_hp[GUARD + idx] = h;
    g_hs[GUARD + idx - 1] = h;
}

// ---------------- conv2: pure-async fp16x2 implicit GEMM over padded rows ----------------
// CTA = 128 oc x one padded row (64 px, xp 1..56 valid). K=1152 in 36 chunks of 32.
// 3-stage cp.async pipeline; swizzled smem; no LDG/STS in loop.
__global__ void __launch_bounds__(256, 3) k_conv2m(float* __restrict__ out) {
    extern __shared__ __align__(128) char dsm[];
    __shared__ int t_bo[1152];       // ((ic*PPLANE + even_off) << 1) | use_shifted
    __shared__ float s_red[256];

    int tid = threadIdx.x, lane = tid & 31, wid = tid >> 5;
    int warp_m = wid & 3, warp_n = wid >> 2;

    for (int k = tid; k < 1152; k += 256) {
        int ic = k / 9, r = k - ic*9;
        int dy = r/3 - 1, dx = r - (r/3)*3 - 1;
        int off = dy*PSTRIDE + dx;
        int sel = off & 1;
        t_bo[k] = ((ic*PPLANE + (off - sel)) << 1) | sel;
    }
    s_red[tid] = 0.f;
    __syncthreads();

    int img = blockIdx.x / 56;
    int yp  = (blockIdx.x - img*56) + 1;        // padded row 1..56
    int pp0 = yp * PSTRIDE;
    size_t ibase = (size_t)img * 128 * PPLANE;
    const __half* HP = g_hp + GUARD;
    const __half* HS = g_hs + GUARD;

    uint32_t sb = smem_u32(dsm);

    // ---- cp.async staging for one k-chunk ----
    #define C2_CPA(s, buf) do { \
        _Pragma("unroll") for (int i = 0; i < 4; i++) { \
            int id = tid + i*256, term = id >> 9, rem = id & 511, row = rem >> 2, c = rem & 3; \
            const __half* src = (term ? g_w2l : g_w2h) + row*1152 + (s)*32 + c*8; \
            uint32_t dst = sb + (buf)*C2_STAGE + term*8192 + row*64 + (((c ^ ((row>>1)&3)) << 4)); \
            CP16(dst, src); } } while (0)
    #define C2_CPB(s, buf) do { \
        _Pragma("unroll") for (int i = 0; i < 4; i++) { \
            int id = tid + i*256, krow = id >> 5, ch = id & 31; \
            int bo = t_bo[(s)*32 + krow]; \
            const __half* base = (bo & 1) ? HS : HP; \
            const __half* src = base + ibase + (bo >> 1) + pp0 + ch*2; \
            uint32_t dst = sb + (buf)*C2_STAGE + C2_BOFF + krow*128 \
                         + (((ch >> 2) ^ (krow & 7)) << 4) + ((ch & 3) << 2); \
            CP4(dst, src); } } while (0)

    // ---- per-thread ldmatrix addressing (swizzled) ----
    uint32_t arow = warp_m*32 + (lane & 15);
    uint32_t aswz = (arow >> 1) & 3;
    uint32_t arb  = arow * 64;
    uint32_t acol = lane >> 4;                         // 0/1 (k 16B-group)
    uint32_t brow = ((lane >> 3) & 1)*8 + (lane & 7);  // k row within 16
    uint32_t bswz = lane & 7;
    uint32_t bg0  = warp_n*4 + (lane >> 4);            // px 16B-group base

    float acc[2][4][4];
    #pragma unroll
    for (int a = 0; a < 2; a++)
        #pragma unroll
        for (int b = 0; b < 4; b++)
            #pragma unroll
            for (int c = 0; c < 4; c++) acc[a][b][c] = 0.f;

    // prologue: stages 0,1
    C2_CPA(0, 0); C2_CPB(0, 0); CPCOMMIT();
    C2_CPA(1, 1); C2_CPB(1, 1); CPCOMMIT();

    for (int s = 0; s < 36; s++) {
        CPWAIT(1);
        __syncthreads();
        int nb = (s + 2) % 3;
        if (s + 2 < 36) { C2_CPA(s + 2, nb); C2_CPB(s + 2, nb); }
        CPCOMMIT();

        uint32_t bufb = sb + (s % 3) * C2_STAGE;
        #pragma unroll
        for (int h = 0; h < 2; h++) {
            uint32_t t[4];
            uint32_t bq[4][2];
            uint32_t bbase = bufb + C2_BOFF + (h*16 + brow)*128;
            ldsm4t(bbase + ((bg0 ^ bswz) << 4), t);
            bq[0][0]=t[0]; bq[0][1]=t[1]; bq[1][0]=t[2]; bq[1][1]=t[3];
            ldsm4t(bbase + (((bg0 + 2) ^ bswz) << 4), t);
            bq[2][0]=t[0]; bq[2][1]=t[1]; bq[3][0]=t[2]; bq[3][1]=t[3];

            uint32_t ac = (((h*2) + acol) ^ aswz) << 4;
            uint32_t am[2][4];
            ldsm4(bufb + arb + ac, am[0]);
            ldsm4(bufb + arb + 1024 + ac, am[1]);
            #pragma unroll
            for (int mt = 0; mt < 2; mt++)
                #pragma unroll
                for (int nt = 0; nt < 4; nt++) mma16816(acc[mt][nt], am[mt], bq[nt]);
            ldsm4(bufb + 8192 + arb + ac, am[0]);
            ldsm4(bufb + 8192 + arb + 1024 + ac, am[1]);
            #pragma unroll
            for (int mt = 0; mt < 2; mt++)
                #pragma unroll
                for (int nt = 0; nt < 4; nt++) mma16816(acc[mt][nt], am[mt], bq[nt]);
        }
    }

    // epilogue: store valid pixels (xp 1..56) + BN2 stats
    int g = lane >> 2, cp = (lane & 3) * 2;
    #pragma unroll
    for (int mt = 0; mt < 2; mt++) {
        #pragma unroll
        for (int hh = 0; hh < 2; hh++) {
            int oc = warp_m*32 + mt*16 + hh*8 + g;
            float sv = 0.f, qv = 0.f;
            float* obase = out + (size_t)(img*128 + oc)*NPIX2 + (yp - 1)*56 - 1;
            #pragma unroll
            for (int nt = 0; nt < 4; nt++) {
                float c0 = acc[mt][nt][hh*2], c1 = acc[mt][nt][hh*2 + 1];
                int xp = warp_n*32 + nt*8 + cp;
                if (xp >= 1 && xp <= 56) { obase[xp] = c0; sv += c0; qv += c0*c0; }
                if (xp + 1 <= 56 && xp + 1 >= 1) { obase[xp + 1] = c1; sv += c1; qv += c1*c1; }
            }
            atomicAdd(&s_red[oc], sv);
            atomicAdd(&s_red[128 + oc], qv);
        }
    }
    __syncthreads();
    if (tid < 128) {
        atomicAdd(&g_sum2[tid], s_red[tid]);
        atomicAdd(&g_sq2[tid],  s_red[128 + tid]);
    }
}

// ---------------- BN2(inline) + ReLU in place ----------------
__global__ void k_bn2(float* __restrict__ out,
                      const float* __restrict__ gamma, const float* __restrict__ beta) {
    int idx = blockIdx.x * 256 + threadIdx.x;
    if (idx >= BATCH * 128 * NPIX2) return;
    int c = (idx / NPIX2) & 127;
    float mean = g_sum2[c] * (1.f / N2F);
    float var  = g_sq2[c]  * (1.f / N2F) - mean * mean;
    float a = __ldg(gamma + c) * rsqrtf(var + 1e-5f);
    float b = __ldg(beta + c) - a * mean;
    out[idx] = fmaxf(fmaf(a, out[idx], b), 0.f);
}

// ---------------- launch ----------------
extern "C" void kernel_launch(void* const* d_in, const int* in_sizes, int n_in,
                              void* d_out, int out_size) {
    const float* inp = (const float*)d_in[0];
    const float* w1  = (const float*)d_in[1];
    const float* g1  = (const float*)d_in[2];
    const float* b1  = (const float*)d_in[3];
    const float* w2  = (const float*)d_in[4];
    const float* g2  = (const float*)d_in[5];
    const float* b2  = (const float*)d_in[6];
    float* out = (float*)d_out;

    cudaFuncSetAttribute(k_conv1m, cudaFuncAttributeMaxDynamicSharedMemorySize, DYN1);
    cudaFuncSetAttribute(k_conv2m, cudaFuncAttributeMaxDynamicSharedMemorySize, C2_DYN);

    k_init<<<576, 256>>>(w1, w2);
    k_conv1m<<<6272, 256, DYN1>>>(inp);
    k_pool<<<(BATCH*128*PPLANE + 255) / 256, 256>>>(g1, b1);
    k_conv2m<<<BATCH*56, 256, C2_DYN>>>(out);
    k_bn2<<<(BATCH*128*NPIX2 + 255) / 256, 256>>>(out, g2, b2);
}